// round 13
// baseline (speedup 1.0000x reference)
#include <cuda_runtime.h>
#include <cstdint>

#define BB 512
#define TT 512
#define SS 64
#define HH 128
#define G3 384
#define BG3 (BB * G3)

__device__ float g_z[(size_t)BB * TT * HH];   // 134 MB
__device__ float g_gx[(size_t)BB * TT * G3];  // 402 MB, layout (T,B,3H)

typedef unsigned long long ull;

__device__ __forceinline__ ull pk2(float lo, float hi) {
    ull r; asm("mov.b64 %0, {%1,%2};" : "=l"(r) : "f"(lo), "f"(hi)); return r;
}
__device__ __forceinline__ float2 upk2(ull v) {
    float2 f; asm("mov.b64 {%0,%1}, %2;" : "=f"(f.x), "=f"(f.y) : "l"(v)); return f;
}
__device__ __forceinline__ ull fma2(ull a, ull b, ull c) {
    ull d; asm("fma.rn.f32x2 %0, %1, %2, %3;" : "=l"(d) : "l"(a), "l"(b), "l"(c)); return d;
}
// sigmoid(x) = 0.5*tanh(x/2)+0.5 via MUFU.TANH (abs err ~5e-4, 10x under budget)
__device__ __forceinline__ float sigap(float x) {
    float y; asm("tanh.approx.f32 %0, %1;" : "=f"(y) : "f"(0.5f * x));
    return fmaf(0.5f, y, 0.5f);
}
__device__ __forceinline__ void cp8(unsigned dst, const float* src) {
    asm volatile("cp.async.ca.shared.global [%0], [%1], 8;" :: "r"(dst), "l"(src));
}
__device__ __forceinline__ void cp16(unsigned dst, const float* src) {
    asm volatile("cp.async.ca.shared.global [%0], [%1], 16;" :: "r"(dst), "l"(src));
}

// ============================================================================
// A1: z = relu(LN(x @ Wf^T + bf)).  (R5 version verbatim — 240us, 2 CTAs/SM)
// 256 threads, weights register-resident, broadcast LDS x-tile.
// ============================================================================
__global__ void __launch_bounds__(256) k_feat(
    const float* __restrict__ x, const float* __restrict__ Wf,
    const float* __restrict__ bf, const float* __restrict__ gf,
    const float* __restrict__ betaf)
{
    __shared__ __align__(16) float xs2[1024];
    __shared__ float fs[2048];
    __shared__ float gfs[128], bes[128];

    const int tid = threadIdx.x, h = tid & 127, gg = tid >> 7;
    const int lane = tid & 31, wid = tid >> 5;

    ull wreg[32];
#pragma unroll
    for (int i = 0; i < 32; ++i) {
        float2 wf = *(const float2*)(Wf + (size_t)h * 64 + 2 * i);
        wreg[i] = pk2(wf.x, wf.y);
    }
    if (tid < 128) { gfs[tid] = gf[tid]; bes[tid] = betaf[tid]; }
    const float bbv = bf[h];

    for (int tile = blockIdx.x; tile < (BB * TT / 16); tile += gridDim.x) {
        const int row0 = tile * 16;
        __syncthreads();
        for (int i = tid; i < 1024; i += 256) {
            int r = i >> 6, s = i & 63;
            xs2[(s >> 1) * 32 + r * 2 + (s & 1)] = x[(size_t)(row0 + r) * 64 + s];
        }
        __syncthreads();

        ull a[8];
#pragma unroll
        for (int p = 0; p < 8; ++p) a[p] = 0ULL;
#pragma unroll
        for (int i = 0; i < 32; ++i) {
            const float* bp2 = xs2 + i * 32 + gg * 16;
            ulonglong2 u01 = *(const ulonglong2*)(bp2);
            ulonglong2 u23 = *(const ulonglong2*)(bp2 + 4);
            ulonglong2 u45 = *(const ulonglong2*)(bp2 + 8);
            ulonglong2 u67 = *(const ulonglong2*)(bp2 + 12);
            a[0] = fma2(wreg[i], u01.x, a[0]); a[1] = fma2(wreg[i], u01.y, a[1]);
            a[2] = fma2(wreg[i], u23.x, a[2]); a[3] = fma2(wreg[i], u23.y, a[3]);
            a[4] = fma2(wreg[i], u45.x, a[4]); a[5] = fma2(wreg[i], u45.y, a[5]);
            a[6] = fma2(wreg[i], u67.x, a[6]); a[7] = fma2(wreg[i], u67.y, a[7]);
        }
#pragma unroll
        for (int p = 0; p < 8; ++p) {
            float2 f = upk2(a[p]);
            fs[(gg * 8 + p) * 128 + h] = f.x + f.y + bbv;
        }
        __syncthreads();

#pragma unroll
        for (int rr = 0; rr < 2; ++rr) {
            const int row = wid * 2 + rr;
            float v[4], s1 = 0.f, s2 = 0.f;
#pragma unroll
            for (int q = 0; q < 4; ++q) {
                v[q] = fs[row * 128 + lane + 32 * q];
                s1 += v[q]; s2 += v[q] * v[q];
            }
#pragma unroll
            for (int o = 16; o > 0; o >>= 1) {
                s1 += __shfl_xor_sync(0xffffffffu, s1, o);
                s2 += __shfl_xor_sync(0xffffffffu, s2, o);
            }
            const float mu = s1 * (1.f / 128.f);
            const float rstd = rsqrtf(s2 * (1.f / 128.f) - mu * mu + 1e-5f);
#pragma unroll
            for (int q = 0; q < 4; ++q) {
                int k = lane + 32 * q;
                float zv = (v[q] - mu) * rstd * gfs[k] + bes[k];
                g_z[(size_t)(row0 + row) * 128 + k] = fmaxf(zv, 0.f);
            }
        }
    }
}

// ============================================================================
// A2: gx = z @ Wih^T + bih -> (T,B,3H).
// 384 threads, wreg[64], 8-row tiles, cp.async double-buffered tile loads.
// ============================================================================
__global__ void __launch_bounds__(384) k_gx(
    const float* __restrict__ Wih, const float* __restrict__ bih)
{
    __shared__ __align__(16) float zs2[2][1024];  // [buf][kp*16 + r*2 + (k&1)]

    const int tid = threadIdx.x, g = tid;
    ull wreg[64];
#pragma unroll
    for (int i = 0; i < 64; ++i) {
        float2 w = *(const float2*)(Wih + (size_t)g * 128 + 2 * i);
        wreg[i] = pk2(w.x, w.y);
    }
    const float bbv = bih[g];
    const unsigned zb_u32 = (unsigned)__cvta_generic_to_shared(&zs2[0][0]);
    const int NT = (BB * TT) / 8;                 // 32768 tiles

    // prefetch first tile into buf 0
    {
        const int row0 = blockIdx.x * 8;
        for (int i = tid; i < 512; i += 384) {
            const int kp = i & 63, r = i >> 6;
            cp8(zb_u32 + (unsigned)(kp * 16 + r * 2) * 4u,
                g_z + (size_t)(row0 + r) * 128 + kp * 2);
        }
    }
    asm volatile("cp.async.commit_group;");

    int cur = 0;
    for (int j = blockIdx.x; j < NT; j += 148) {
        asm volatile("cp.async.wait_group 0;");
        __syncthreads();

        const int jn = j + 148;
        if (jn < NT) {
            const int row0n = jn * 8;
            const unsigned base = zb_u32 + (unsigned)(cur ^ 1) * 4096u;
            for (int i = tid; i < 512; i += 384) {
                const int kp = i & 63, r = i >> 6;
                cp8(base + (unsigned)(kp * 16 + r * 2) * 4u,
                    g_z + (size_t)(row0n + r) * 128 + kp * 2);
            }
        }
        asm volatile("cp.async.commit_group;");

        const float* zc = &zs2[cur][0];
        ull a[8];
#pragma unroll
        for (int p = 0; p < 8; ++p) a[p] = pk2(bbv, 0.f);
#pragma unroll
        for (int i = 0; i < 64; ++i) {
            const float* bp2 = zc + i * 16;
            ulonglong2 u01 = *(const ulonglong2*)(bp2);
            ulonglong2 u23 = *(const ulonglong2*)(bp2 + 4);
            ulonglong2 u45 = *(const ulonglong2*)(bp2 + 8);
            ulonglong2 u67 = *(const ulonglong2*)(bp2 + 12);
            a[0] = fma2(wreg[i], u01.x, a[0]); a[1] = fma2(wreg[i], u01.y, a[1]);
            a[2] = fma2(wreg[i], u23.x, a[2]); a[3] = fma2(wreg[i], u23.y, a[3]);
            a[4] = fma2(wreg[i], u45.x, a[4]); a[5] = fma2(wreg[i], u45.y, a[5]);
            a[6] = fma2(wreg[i], u67.x, a[6]); a[7] = fma2(wreg[i], u67.y, a[7]);
        }
        const int row0 = j * 8;
        const int b = row0 >> 9, t0 = row0 & 511;   // 8 | 512 => same b for tile
        const size_t base_o = (size_t)t0 * BG3 + (size_t)b * G3 + g;
#pragma unroll
        for (int p = 0; p < 8; ++p) {
            float2 f = upk2(a[p]);
            g_gx[base_o + (size_t)p * BG3] = f.x + f.y;
        }
        cur ^= 1;
    }
}

// ============================================================================
// B: sequential GRU scan. 128 CTAs x 4 rows, 384 threads (thread-per-gate).
// W_hh register-resident (wreg[64]); gx via cp.async 4-slot ring; LN folded
// into precomputed head weights (GW/SG/BWB); 2 barriers/step.
// ============================================================================
__global__ void __launch_bounds__(384) k_gru(
    const float* __restrict__ hx, const int* __restrict__ done,
    const float* __restrict__ Whh, const float* __restrict__ bhh,
    const float* __restrict__ gr, const float* __restrict__ betar,
    const float* __restrict__ Wpol, const float* __restrict__ bpol,
    const float* __restrict__ Wval, const float* __restrict__ bval,
    float* __restrict__ out)
{
    __shared__ __align__(16) float hs2[512];      // [(k>>1)*8 + r*2 + (k&1)]
    __shared__ __align__(16) float Hn[512];       // [r][128] h_new (pre-mask)
    __shared__ __align__(16) float4 Rs4[128];     // [k]: rows 0..3
    __shared__ __align__(16) float4 Us4[128];
    __shared__ float D1[2048];                    // [r][512] (1 - done)
    __shared__ float2 Pr[16];                     // [warp8..11][row]
    __shared__ float GW[1152];                    // [o][128] = g_r * W_head
    __shared__ float SG[9], BWB[9];               // sum(GW), sum(beta*W)+bias
    __shared__ __align__(16) float gxs[4 * 1536]; // gx ring: 4 steps x [r][384]

    const int tid = threadIdx.x, g = tid;
    const int lane = tid & 31, wid = tid >> 5;
    const int b0 = blockIdx.x * 4;

    ull wreg[64];
#pragma unroll
    for (int i = 0; i < 64; ++i) {
        float2 w = *(const float2*)(Whh + (size_t)g * 128 + 2 * i);
        wreg[i] = pk2(w.x, w.y);
    }
    const float bhg = bhh[g];

    for (int i = tid; i < 512; i += 384) {
        const int r = i >> 7, k = i & 127;
        hs2[(k >> 1) * 8 + r * 2 + (k & 1)] = hx[(size_t)(b0 + r) * 128 + k];
    }
    for (int i = tid; i < 2048; i += 384) {
        const int r = i >> 9, t = i & 511;
        D1[i] = 1.0f - (float)done[(size_t)(b0 + r) * 512 + t];
    }
    for (int i = tid; i < 1152; i += 384) {
        const int k = i & 127;
        GW[i] = gr[k] * ((i < 1024) ? Wpol[i] : Wval[k]);
    }
    __syncthreads();
    if (wid < 9) {                                // head constants: SG, BWB
        const int o = wid;
        float s = 0.f, b2 = 0.f;
#pragma unroll
        for (int q = 0; q < 4; ++q) {
            const int k = lane + 32 * q;
            const float wv = (o < 8) ? Wpol[o * 128 + k] : Wval[k];
            s += GW[o * 128 + k];
            b2 += betar[k] * wv;
        }
#pragma unroll
        for (int o2 = 16; o2 > 0; o2 >>= 1) {
            s  += __shfl_xor_sync(0xffffffffu, s,  o2);
            b2 += __shfl_xor_sync(0xffffffffu, b2, o2);
        }
        if (lane == 0) {
            SG[o] = s;
            BWB[o] = b2 + ((o < 8) ? bpol[o] : bval[0]);
        }
    }

    // gx ring bootstrap: prefetch steps 0 and 1 (16B per thread per step)
    const unsigned gxs_u32 = (unsigned)__cvta_generic_to_shared(gxs);
#pragma unroll
    for (int q = 0; q < 2; ++q) {
        cp16(gxs_u32 + (unsigned)(q * 1536 + tid * 4) * 4u,
             g_gx + (size_t)q * BG3 + (size_t)b0 * G3 + tid * 4);
        asm volatile("cp.async.commit_group;");
    }
    asm volatile("cp.async.wait_group 1;");
    __syncthreads();

    const int kk = g - 256;                       // n-gate h index (g>=256)
    const int hb = (kk >= 0) ? ((kk >> 1) * 8 + (kk & 1)) : 0;
    const int p4row = (wid < 12) ? (wid / 3) : 0; // P4: warp -> (row, 3 outs)
    const int p4o0 = (wid < 12) ? ((wid - p4row * 3) * 3) : 0;

    for (int t = 0; t < 512; ++t) {
        const float* gxc = gxs + (t & 3) * 1536;

        // prefetch gx(t+2) — overlaps P1
        if (t + 2 < 512) {
            cp16(gxs_u32 + (unsigned)(((t + 2) & 3) * 1536 + tid * 4) * 4u,
                 g_gx + (size_t)(t + 2) * BG3 + (size_t)b0 * G3 + tid * 4);
        }
        asm volatile("cp.async.commit_group;");

        // ---- P1: gh = W_hh @ h + b_hh (bias folded into acc init)
        ull a0 = pk2(bhg, 0.f), a1 = pk2(bhg, 0.f);
        ull a2 = pk2(bhg, 0.f), a3 = pk2(bhg, 0.f);
#pragma unroll
        for (int i = 0; i < 64; ++i) {
            ulonglong2 u01 = *(const ulonglong2*)(hs2 + i * 8);
            ulonglong2 u23 = *(const ulonglong2*)(hs2 + i * 8 + 4);
            a0 = fma2(wreg[i], u01.x, a0);
            a1 = fma2(wreg[i], u01.y, a1);
            a2 = fma2(wreg[i], u23.x, a2);
            a3 = fma2(wreg[i], u23.y, a3);
        }
        float2 f0 = upk2(a0), f1 = upk2(a1), f2 = upk2(a2), f3 = upk2(a3);
        const float gh0 = f0.x + f0.y, gh1 = f1.x + f1.y;
        const float gh2 = f2.x + f2.y, gh3 = f3.x + f3.y;

        // ---- P2: r / u gates (fast sigmoid)
        if (g < 128) {
            float4 rv;
            rv.x = sigap(gxc[0 * 384 + g] + gh0);
            rv.y = sigap(gxc[1 * 384 + g] + gh1);
            rv.z = sigap(gxc[2 * 384 + g] + gh2);
            rv.w = sigap(gxc[3 * 384 + g] + gh3);
            Rs4[g] = rv;
        } else if (g < 256) {
            float4 uv;
            const int q = g - 128;
            uv.x = sigap(gxc[0 * 384 + g] + gh0);
            uv.y = sigap(gxc[1 * 384 + g] + gh1);
            uv.z = sigap(gxc[2 * 384 + g] + gh2);
            uv.w = sigap(gxc[3 * 384 + g] + gh3);
            Us4[q] = uv;
        }
        __syncthreads();   // SYNC_A

        // ---- P3: n gate, h update, LN partials (warps 8..11)
        if (g >= 256) {
            const float4 rr = Rs4[kk];
            const float4 uu = Us4[kk];
            float s[4], q2[4];
            {
                const float hprev = hs2[hb + 0];
                const float n = tanhf(gxc[0 * 384 + g] + rr.x * gh0);
                const float hv = (1.f - uu.x) * n + uu.x * hprev;
                Hn[0 * 128 + kk] = hv; hs2[hb + 0] = hv * D1[t];
                s[0] = hv; q2[0] = hv * hv;
            }
            {
                const float hprev = hs2[hb + 2];
                const float n = tanhf(gxc[1 * 384 + g] + rr.y * gh1);
                const float hv = (1.f - uu.y) * n + uu.y * hprev;
                Hn[1 * 128 + kk] = hv; hs2[hb + 2] = hv * D1[512 + t];
                s[1] = hv; q2[1] = hv * hv;
            }
            {
                const float hprev = hs2[hb + 4];
                const float n = tanhf(gxc[2 * 384 + g] + rr.z * gh2);
                const float hv = (1.f - uu.z) * n + uu.z * hprev;
                Hn[2 * 128 + kk] = hv; hs2[hb + 4] = hv * D1[1024 + t];
                s[2] = hv; q2[2] = hv * hv;
            }
            {
                const float hprev = hs2[hb + 6];
                const float n = tanhf(gxc[3 * 384 + g] + rr.w * gh3);
                const float hv = (1.f - uu.w) * n + uu.w * hprev;
                Hn[3 * 128 + kk] = hv; hs2[hb + 6] = hv * D1[1536 + t];
                s[3] = hv; q2[3] = hv * hv;
            }
#pragma unroll
            for (int o = 16; o > 0; o >>= 1) {
#pragma unroll
                for (int r = 0; r < 4; ++r) {
                    s[r]  += __shfl_xor_sync(0xffffffffu, s[r],  o);
                    q2[r] += __shfl_xor_sync(0xffffffffu, q2[r], o);
                }
            }
            if (lane == 0) {
                const int wi = wid - 8;
#pragma unroll
                for (int r = 0; r < 4; ++r)
                    Pr[wi * 4 + r] = make_float2(s[r], q2[r]);
            }
        }
        asm volatile("cp.async.wait_group 1;");   // gx(t+1) landed
        __syncthreads();   // SYNC_B

        // ---- P4: heads with LN folded in. warp -> (row, 3 outputs)
        if (wid < 12) {
            float sum = 0.f, sq = 0.f;
#pragma unroll
            for (int wi = 0; wi < 4; ++wi) {
                float2 pp = Pr[wi * 4 + p4row];
                sum += pp.x; sq += pp.y;
            }
            const float mu = sum * (1.f / 128.f);
            const float rstd = rsqrtf(sq * (1.f / 128.f) - mu * mu + 1e-5f);
            float hn[4];
#pragma unroll
            for (int q = 0; q < 4; ++q) hn[q] = Hn[p4row * 128 + lane + 32 * q];
            float acc[3] = {0.f, 0.f, 0.f};
#pragma unroll
            for (int j = 0; j < 3; ++j)
#pragma unroll
                for (int q = 0; q < 4; ++q)
                    acc[j] += hn[q] * GW[(p4o0 + j) * 128 + lane + 32 * q];
#pragma unroll
            for (int o2 = 16; o2 > 0; o2 >>= 1) {
#pragma unroll
                for (int j = 0; j < 3; ++j)
                    acc[j] += __shfl_xor_sync(0xffffffffu, acc[j], o2);
            }
            if (lane == 0) {
#pragma unroll
                for (int j = 0; j < 3; ++j) {
                    const int o = p4o0 + j;
                    const float val = rstd * (acc[j] - mu * SG[o]) + BWB[o];
                    if (o < 8)
                        out[(size_t)(b0 + p4row) * 4096 + (size_t)t * 8 + o] = val;
                    else
                        out[(size_t)2097152 + (size_t)(b0 + p4row) * 512 + t] = val;
                }
            }
        }
    }

    // h_fin = masked carry (hs2 published by final SYNC_B)
    for (int i = tid; i < 512; i += 384) {
        const int r = i >> 7, k = i & 127;
        out[(size_t)2359296 + (size_t)(b0 + r) * 128 + k] =
            hs2[(k >> 1) * 8 + r * 2 + (k & 1)];
    }
}

extern "C" void kernel_launch(void* const* d_in, const int* in_sizes, int n_in,
                              void* d_out, int out_size)
{
    const float* x     = (const float*)d_in[0];
    const float* hx    = (const float*)d_in[1];
    const int*   done  = (const int*)d_in[2];
    const float* Wf    = (const float*)d_in[3];
    const float* bf    = (const float*)d_in[4];
    const float* gf    = (const float*)d_in[5];
    const float* betaf = (const float*)d_in[6];
    const float* Wih   = (const float*)d_in[7];
    const float* Whh   = (const float*)d_in[8];
    const float* bih   = (const float*)d_in[9];
    const float* bhh   = (const float*)d_in[10];
    const float* gr    = (const float*)d_in[11];
    const float* betar = (const float*)d_in[12];
    const float* Wpol  = (const float*)d_in[13];
    const float* bpol  = (const float*)d_in[14];
    const float* Wval  = (const float*)d_in[15];
    const float* bval  = (const float*)d_in[16];
    float* out = (float*)d_out;

    k_feat<<<296, 256>>>(x, Wf, bf, gf, betaf);
    k_gx<<<148, 384>>>(Wih, bih);
    k_gru<<<128, 384>>>(hx, done, Whh, bhh, gr, betar, Wpol, bpol, Wval, bval, out);
}

// round 14
// speedup vs baseline: 1.0034x; 1.0034x over previous
#include <cuda_runtime.h>
#include <cstdint>

#define BB 512
#define TT 512
#define SS 64
#define HH 128
#define G3 384
#define BG3 (BB * G3)

__device__ float g_z[(size_t)BB * TT * HH];   // 134 MB
__device__ float g_gx[(size_t)BB * TT * G3];  // 402 MB, layout (T,B,3H)

typedef unsigned long long ull;

__device__ __forceinline__ ull pk2(float lo, float hi) {
    ull r; asm("mov.b64 %0, {%1,%2};" : "=l"(r) : "f"(lo), "f"(hi)); return r;
}
__device__ __forceinline__ float2 upk2(ull v) {
    float2 f; asm("mov.b64 {%0,%1}, %2;" : "=f"(f.x), "=f"(f.y) : "l"(v)); return f;
}
__device__ __forceinline__ ull fma2(ull a, ull b, ull c) {
    ull d; asm("fma.rn.f32x2 %0, %1, %2, %3;" : "=l"(d) : "l"(a), "l"(b), "l"(c)); return d;
}
// sigmoid(x) = 0.5*tanh(x/2)+0.5 via MUFU.TANH (abs err ~5e-4, 10x under budget)
__device__ __forceinline__ float sigap(float x) {
    float y; asm("tanh.approx.f32 %0, %1;" : "=f"(y) : "f"(0.5f * x));
    return fmaf(0.5f, y, 0.5f);
}
__device__ __forceinline__ void cp8(unsigned dst, const float* src) {
    asm volatile("cp.async.ca.shared.global [%0], [%1], 8;" :: "r"(dst), "l"(src));
}
__device__ __forceinline__ void cp16(unsigned dst, const float* src) {
    asm volatile("cp.async.ca.shared.global [%0], [%1], 16;" :: "r"(dst), "l"(src));
}

// ============================================================================
// A1: z = relu(LN(x @ Wf^T + bf)).  (R5 version verbatim — 240us, 2 CTAs/SM)
// 256 threads, weights register-resident, broadcast LDS x-tile.
// ============================================================================
__global__ void __launch_bounds__(256) k_feat(
    const float* __restrict__ x, const float* __restrict__ Wf,
    const float* __restrict__ bf, const float* __restrict__ gf,
    const float* __restrict__ betaf)
{
    __shared__ __align__(16) float xs2[1024];
    __shared__ float fs[2048];
    __shared__ float gfs[128], bes[128];

    const int tid = threadIdx.x, h = tid & 127, gg = tid >> 7;
    const int lane = tid & 31, wid = tid >> 5;

    ull wreg[32];
#pragma unroll
    for (int i = 0; i < 32; ++i) {
        float2 wf = *(const float2*)(Wf + (size_t)h * 64 + 2 * i);
        wreg[i] = pk2(wf.x, wf.y);
    }
    if (tid < 128) { gfs[tid] = gf[tid]; bes[tid] = betaf[tid]; }
    const float bbv = bf[h];

    for (int tile = blockIdx.x; tile < (BB * TT / 16); tile += gridDim.x) {
        const int row0 = tile * 16;
        __syncthreads();
        for (int i = tid; i < 1024; i += 256) {
            int r = i >> 6, s = i & 63;
            xs2[(s >> 1) * 32 + r * 2 + (s & 1)] = x[(size_t)(row0 + r) * 64 + s];
        }
        __syncthreads();

        ull a[8];
#pragma unroll
        for (int p = 0; p < 8; ++p) a[p] = 0ULL;
#pragma unroll
        for (int i = 0; i < 32; ++i) {
            const float* bp2 = xs2 + i * 32 + gg * 16;
            ulonglong2 u01 = *(const ulonglong2*)(bp2);
            ulonglong2 u23 = *(const ulonglong2*)(bp2 + 4);
            ulonglong2 u45 = *(const ulonglong2*)(bp2 + 8);
            ulonglong2 u67 = *(const ulonglong2*)(bp2 + 12);
            a[0] = fma2(wreg[i], u01.x, a[0]); a[1] = fma2(wreg[i], u01.y, a[1]);
            a[2] = fma2(wreg[i], u23.x, a[2]); a[3] = fma2(wreg[i], u23.y, a[3]);
            a[4] = fma2(wreg[i], u45.x, a[4]); a[5] = fma2(wreg[i], u45.y, a[5]);
            a[6] = fma2(wreg[i], u67.x, a[6]); a[7] = fma2(wreg[i], u67.y, a[7]);
        }
#pragma unroll
        for (int p = 0; p < 8; ++p) {
            float2 f = upk2(a[p]);
            fs[(gg * 8 + p) * 128 + h] = f.x + f.y + bbv;
        }
        __syncthreads();

#pragma unroll
        for (int rr = 0; rr < 2; ++rr) {
            const int row = wid * 2 + rr;
            float v[4], s1 = 0.f, s2 = 0.f;
#pragma unroll
            for (int q = 0; q < 4; ++q) {
                v[q] = fs[row * 128 + lane + 32 * q];
                s1 += v[q]; s2 += v[q] * v[q];
            }
#pragma unroll
            for (int o = 16; o > 0; o >>= 1) {
                s1 += __shfl_xor_sync(0xffffffffu, s1, o);
                s2 += __shfl_xor_sync(0xffffffffu, s2, o);
            }
            const float mu = s1 * (1.f / 128.f);
            const float rstd = rsqrtf(s2 * (1.f / 128.f) - mu * mu + 1e-5f);
#pragma unroll
            for (int q = 0; q < 4; ++q) {
                int k = lane + 32 * q;
                float zv = (v[q] - mu) * rstd * gfs[k] + bes[k];
                g_z[(size_t)(row0 + row) * 128 + k] = fmaxf(zv, 0.f);
            }
        }
    }
}

// ============================================================================
// A2: gx = z @ Wih^T + bih -> (T,B,3H).
// 384 threads, wreg[64], 8-row tiles, cp.async double-buffered tile loads.
// ============================================================================
__global__ void __launch_bounds__(384) k_gx(
    const float* __restrict__ Wih, const float* __restrict__ bih)
{
    __shared__ __align__(16) float zs2[2][1024];  // [buf][kp*16 + r*2 + (k&1)]

    const int tid = threadIdx.x, g = tid;
    ull wreg[64];
#pragma unroll
    for (int i = 0; i < 64; ++i) {
        float2 w = *(const float2*)(Wih + (size_t)g * 128 + 2 * i);
        wreg[i] = pk2(w.x, w.y);
    }
    const float bbv = bih[g];
    const unsigned zb_u32 = (unsigned)__cvta_generic_to_shared(&zs2[0][0]);
    const int NT = (BB * TT) / 8;                 // 32768 tiles

    // prefetch first tile into buf 0
    {
        const int row0 = blockIdx.x * 8;
        for (int i = tid; i < 512; i += 384) {
            const int kp = i & 63, r = i >> 6;
            cp8(zb_u32 + (unsigned)(kp * 16 + r * 2) * 4u,
                g_z + (size_t)(row0 + r) * 128 + kp * 2);
        }
    }
    asm volatile("cp.async.commit_group;");

    int cur = 0;
    for (int j = blockIdx.x; j < NT; j += 148) {
        asm volatile("cp.async.wait_group 0;");
        __syncthreads();

        const int jn = j + 148;
        if (jn < NT) {
            const int row0n = jn * 8;
            const unsigned base = zb_u32 + (unsigned)(cur ^ 1) * 4096u;
            for (int i = tid; i < 512; i += 384) {
                const int kp = i & 63, r = i >> 6;
                cp8(base + (unsigned)(kp * 16 + r * 2) * 4u,
                    g_z + (size_t)(row0n + r) * 128 + kp * 2);
            }
        }
        asm volatile("cp.async.commit_group;");

        const float* zc = &zs2[cur][0];
        ull a[8];
#pragma unroll
        for (int p = 0; p < 8; ++p) a[p] = pk2(bbv, 0.f);
#pragma unroll
        for (int i = 0; i < 64; ++i) {
            const float* bp2 = zc + i * 16;
            ulonglong2 u01 = *(const ulonglong2*)(bp2);
            ulonglong2 u23 = *(const ulonglong2*)(bp2 + 4);
            ulonglong2 u45 = *(const ulonglong2*)(bp2 + 8);
            ulonglong2 u67 = *(const ulonglong2*)(bp2 + 12);
            a[0] = fma2(wreg[i], u01.x, a[0]); a[1] = fma2(wreg[i], u01.y, a[1]);
            a[2] = fma2(wreg[i], u23.x, a[2]); a[3] = fma2(wreg[i], u23.y, a[3]);
            a[4] = fma2(wreg[i], u45.x, a[4]); a[5] = fma2(wreg[i], u45.y, a[5]);
            a[6] = fma2(wreg[i], u67.x, a[6]); a[7] = fma2(wreg[i], u67.y, a[7]);
        }
        const int row0 = j * 8;
        const int b = row0 >> 9, t0 = row0 & 511;   // 8 | 512 => same b for tile
        const size_t base_o = (size_t)t0 * BG3 + (size_t)b * G3 + g;
#pragma unroll
        for (int p = 0; p < 8; ++p) {
            float2 f = upk2(a[p]);
            g_gx[base_o + (size_t)p * BG3] = f.x + f.y;
        }
        cur ^= 1;
    }
}

// ============================================================================
// B: sequential GRU scan. 128 CTAs x 4 rows, 384 threads (thread-per-gate).
// W_hh register-resident (wreg[64]); gx via cp.async 4-slot ring; LN folded
// into precomputed head weights (GW/SG/BWB); 2 barriers/step.
// ============================================================================
__global__ void __launch_bounds__(384) k_gru(
    const float* __restrict__ hx, const int* __restrict__ done,
    const float* __restrict__ Whh, const float* __restrict__ bhh,
    const float* __restrict__ gr, const float* __restrict__ betar,
    const float* __restrict__ Wpol, const float* __restrict__ bpol,
    const float* __restrict__ Wval, const float* __restrict__ bval,
    float* __restrict__ out)
{
    __shared__ __align__(16) float hs2[512];      // [(k>>1)*8 + r*2 + (k&1)]
    __shared__ __align__(16) float Hn[512];       // [r][128] h_new (pre-mask)
    __shared__ __align__(16) float4 Rs4[128];     // [k]: rows 0..3
    __shared__ __align__(16) float4 Us4[128];
    __shared__ float D1[2048];                    // [r][512] (1 - done)
    __shared__ float2 Pr[16];                     // [warp8..11][row]
    __shared__ float GW[1152];                    // [o][128] = g_r * W_head
    __shared__ float SG[9], BWB[9];               // sum(GW), sum(beta*W)+bias
    __shared__ __align__(16) float gxs[4 * 1536]; // gx ring: 4 steps x [r][384]

    const int tid = threadIdx.x, g = tid;
    const int lane = tid & 31, wid = tid >> 5;
    const int b0 = blockIdx.x * 4;

    ull wreg[64];
#pragma unroll
    for (int i = 0; i < 64; ++i) {
        float2 w = *(const float2*)(Whh + (size_t)g * 128 + 2 * i);
        wreg[i] = pk2(w.x, w.y);
    }
    const float bhg = bhh[g];

    for (int i = tid; i < 512; i += 384) {
        const int r = i >> 7, k = i & 127;
        hs2[(k >> 1) * 8 + r * 2 + (k & 1)] = hx[(size_t)(b0 + r) * 128 + k];
    }
    for (int i = tid; i < 2048; i += 384) {
        const int r = i >> 9, t = i & 511;
        D1[i] = 1.0f - (float)done[(size_t)(b0 + r) * 512 + t];
    }
    for (int i = tid; i < 1152; i += 384) {
        const int k = i & 127;
        GW[i] = gr[k] * ((i < 1024) ? Wpol[i] : Wval[k]);
    }
    __syncthreads();
    if (wid < 9) {                                // head constants: SG, BWB
        const int o = wid;
        float s = 0.f, b2 = 0.f;
#pragma unroll
        for (int q = 0; q < 4; ++q) {
            const int k = lane + 32 * q;
            const float wv = (o < 8) ? Wpol[o * 128 + k] : Wval[k];
            s += GW[o * 128 + k];
            b2 += betar[k] * wv;
        }
#pragma unroll
        for (int o2 = 16; o2 > 0; o2 >>= 1) {
            s  += __shfl_xor_sync(0xffffffffu, s,  o2);
            b2 += __shfl_xor_sync(0xffffffffu, b2, o2);
        }
        if (lane == 0) {
            SG[o] = s;
            BWB[o] = b2 + ((o < 8) ? bpol[o] : bval[0]);
        }
    }

    // gx ring bootstrap: prefetch steps 0 and 1 (16B per thread per step)
    const unsigned gxs_u32 = (unsigned)__cvta_generic_to_shared(gxs);
#pragma unroll
    for (int q = 0; q < 2; ++q) {
        cp16(gxs_u32 + (unsigned)(q * 1536 + tid * 4) * 4u,
             g_gx + (size_t)q * BG3 + (size_t)b0 * G3 + tid * 4);
        asm volatile("cp.async.commit_group;");
    }
    asm volatile("cp.async.wait_group 1;");
    __syncthreads();

    const int kk = g - 256;                       // n-gate h index (g>=256)
    const int hb = (kk >= 0) ? ((kk >> 1) * 8 + (kk & 1)) : 0;
    const int p4row = (wid < 12) ? (wid / 3) : 0; // P4: warp -> (row, 3 outs)
    const int p4o0 = (wid < 12) ? ((wid - p4row * 3) * 3) : 0;

    for (int t = 0; t < 512; ++t) {
        const float* gxc = gxs + (t & 3) * 1536;

        // prefetch gx(t+2) — overlaps P1
        if (t + 2 < 512) {
            cp16(gxs_u32 + (unsigned)(((t + 2) & 3) * 1536 + tid * 4) * 4u,
                 g_gx + (size_t)(t + 2) * BG3 + (size_t)b0 * G3 + tid * 4);
        }
        asm volatile("cp.async.commit_group;");

        // ---- P1: gh = W_hh @ h + b_hh (bias folded into acc init)
        ull a0 = pk2(bhg, 0.f), a1 = pk2(bhg, 0.f);
        ull a2 = pk2(bhg, 0.f), a3 = pk2(bhg, 0.f);
#pragma unroll
        for (int i = 0; i < 64; ++i) {
            ulonglong2 u01 = *(const ulonglong2*)(hs2 + i * 8);
            ulonglong2 u23 = *(const ulonglong2*)(hs2 + i * 8 + 4);
            a0 = fma2(wreg[i], u01.x, a0);
            a1 = fma2(wreg[i], u01.y, a1);
            a2 = fma2(wreg[i], u23.x, a2);
            a3 = fma2(wreg[i], u23.y, a3);
        }
        float2 f0 = upk2(a0), f1 = upk2(a1), f2 = upk2(a2), f3 = upk2(a3);
        const float gh0 = f0.x + f0.y, gh1 = f1.x + f1.y;
        const float gh2 = f2.x + f2.y, gh3 = f3.x + f3.y;

        // ---- P2: r / u gates (fast sigmoid)
        if (g < 128) {
            float4 rv;
            rv.x = sigap(gxc[0 * 384 + g] + gh0);
            rv.y = sigap(gxc[1 * 384 + g] + gh1);
            rv.z = sigap(gxc[2 * 384 + g] + gh2);
            rv.w = sigap(gxc[3 * 384 + g] + gh3);
            Rs4[g] = rv;
        } else if (g < 256) {
            float4 uv;
            const int q = g - 128;
            uv.x = sigap(gxc[0 * 384 + g] + gh0);
            uv.y = sigap(gxc[1 * 384 + g] + gh1);
            uv.z = sigap(gxc[2 * 384 + g] + gh2);
            uv.w = sigap(gxc[3 * 384 + g] + gh3);
            Us4[q] = uv;
        }
        __syncthreads();   // SYNC_A

        // ---- P3: n gate, h update, LN partials (warps 8..11)
        if (g >= 256) {
            const float4 rr = Rs4[kk];
            const float4 uu = Us4[kk];
            float s[4], q2[4];
            {
                const float hprev = hs2[hb + 0];
                const float n = tanhf(gxc[0 * 384 + g] + rr.x * gh0);
                const float hv = (1.f - uu.x) * n + uu.x * hprev;
                Hn[0 * 128 + kk] = hv; hs2[hb + 0] = hv * D1[t];
                s[0] = hv; q2[0] = hv * hv;
            }
            {
                const float hprev = hs2[hb + 2];
                const float n = tanhf(gxc[1 * 384 + g] + rr.y * gh1);
                const float hv = (1.f - uu.y) * n + uu.y * hprev;
                Hn[1 * 128 + kk] = hv; hs2[hb + 2] = hv * D1[512 + t];
                s[1] = hv; q2[1] = hv * hv;
            }
            {
                const float hprev = hs2[hb + 4];
                const float n = tanhf(gxc[2 * 384 + g] + rr.z * gh2);
                const float hv = (1.f - uu.z) * n + uu.z * hprev;
                Hn[2 * 128 + kk] = hv; hs2[hb + 4] = hv * D1[1024 + t];
                s[2] = hv; q2[2] = hv * hv;
            }
            {
                const float hprev = hs2[hb + 6];
                const float n = tanhf(gxc[3 * 384 + g] + rr.w * gh3);
                const float hv = (1.f - uu.w) * n + uu.w * hprev;
                Hn[3 * 128 + kk] = hv; hs2[hb + 6] = hv * D1[1536 + t];
                s[3] = hv; q2[3] = hv * hv;
            }
#pragma unroll
            for (int o = 16; o > 0; o >>= 1) {
#pragma unroll
                for (int r = 0; r < 4; ++r) {
                    s[r]  += __shfl_xor_sync(0xffffffffu, s[r],  o);
                    q2[r] += __shfl_xor_sync(0xffffffffu, q2[r], o);
                }
            }
            if (lane == 0) {
                const int wi = wid - 8;
#pragma unroll
                for (int r = 0; r < 4; ++r)
                    Pr[wi * 4 + r] = make_float2(s[r], q2[r]);
            }
        }
        asm volatile("cp.async.wait_group 1;");   // gx(t+1) landed
        __syncthreads();   // SYNC_B

        // ---- P4: heads with LN folded in. warp -> (row, 3 outputs)
        if (wid < 12) {
            float sum = 0.f, sq = 0.f;
#pragma unroll
            for (int wi = 0; wi < 4; ++wi) {
                float2 pp = Pr[wi * 4 + p4row];
                sum += pp.x; sq += pp.y;
            }
            const float mu = sum * (1.f / 128.f);
            const float rstd = rsqrtf(sq * (1.f / 128.f) - mu * mu + 1e-5f);
            float hn[4];
#pragma unroll
            for (int q = 0; q < 4; ++q) hn[q] = Hn[p4row * 128 + lane + 32 * q];
            float acc[3] = {0.f, 0.f, 0.f};
#pragma unroll
            for (int j = 0; j < 3; ++j)
#pragma unroll
                for (int q = 0; q < 4; ++q)
                    acc[j] += hn[q] * GW[(p4o0 + j) * 128 + lane + 32 * q];
#pragma unroll
            for (int o2 = 16; o2 > 0; o2 >>= 1) {
#pragma unroll
                for (int j = 0; j < 3; ++j)
                    acc[j] += __shfl_xor_sync(0xffffffffu, acc[j], o2);
            }
            if (lane == 0) {
#pragma unroll
                for (int j = 0; j < 3; ++j) {
                    const int o = p4o0 + j;
                    const float val = rstd * (acc[j] - mu * SG[o]) + BWB[o];
                    if (o < 8)
                        out[(size_t)(b0 + p4row) * 4096 + (size_t)t * 8 + o] = val;
                    else
                        out[(size_t)2097152 + (size_t)(b0 + p4row) * 512 + t] = val;
                }
            }
        }
    }

    // h_fin = masked carry (hs2 published by final SYNC_B)
    for (int i = tid; i < 512; i += 384) {
        const int r = i >> 7, k = i & 127;
        out[(size_t)2359296 + (size_t)(b0 + r) * 128 + k] =
            hs2[(k >> 1) * 8 + r * 2 + (k & 1)];
    }
}

extern "C" void kernel_launch(void* const* d_in, const int* in_sizes, int n_in,
                              void* d_out, int out_size)
{
    const float* x     = (const float*)d_in[0];
    const float* hx    = (const float*)d_in[1];
    const int*   done  = (const int*)d_in[2];
    const float* Wf    = (const float*)d_in[3];
    const float* bf    = (const float*)d_in[4];
    const float* gf    = (const float*)d_in[5];
    const float* betaf = (const float*)d_in[6];
    const float* Wih   = (const float*)d_in[7];
    const float* Whh   = (const float*)d_in[8];
    const float* bih   = (const float*)d_in[9];
    const float* bhh   = (const float*)d_in[10];
    const float* gr    = (const float*)d_in[11];
    const float* betar = (const float*)d_in[12];
    const float* Wpol  = (const float*)d_in[13];
    const float* bpol  = (const float*)d_in[14];
    const float* Wval  = (const float*)d_in[15];
    const float* bval  = (const float*)d_in[16];
    float* out = (float*)d_out;

    k_feat<<<296, 256>>>(x, Wf, bf, gf, betaf);
    k_gx<<<148, 384>>>(Wih, bih);
    k_gru<<<128, 384>>>(hx, done, Whh, bhh, gr, betar, Wpol, bpol, Wval, bval, out);
}